// round 6
// baseline (speedup 1.0000x reference)
#include <cuda_runtime.h>
#include <stdint.h>

// FP32 bit-pulse -> FP8 E4M3 bit-pulse converter.
// Input : N*32 floats (0.0f/1.0f), row = [S, E7..E0, M22..M0] MSB first
// Output: N*8  floats, row = [S, E3..E0, M2..M0]
//
// Round-3/5 warp-cooperative smem nibble transpose, made PERSISTENT:
// one wave of blocks (148 SMs x 8 blocks), each warp grid-strides over ~7
// 32-row tiles. No state is held across tiles (regs stay ~32, occ ~81%),
// removing the ~6 wave-transition drain/refill bubbles of the 8192-block
// launch while keeping the DRAM read queue continuously fed.

__device__ __forceinline__ void convert_row(uint32_t packed,
                                            float4& o0, float4& o1)
{
    uint32_t s    = packed >> 31;
    uint32_t exp  = (packed >> 23) & 0xFFu;
    uint32_t mant = packed & 0x7FFFFFu;

    // normal path: RNE round 23 -> 3 mantissa bits
    uint32_t kept = mant >> 20;
    uint32_t R    = (mant >> 19) & 1u;
    uint32_t S    = (mant & ((1u << 19) - 1u)) != 0u;
    uint32_t L    = kept & 1u;
    uint32_t mr   = kept + (R & (S | L));
    uint32_t carry = mr >> 3;
    uint32_t mant_norm = carry ? 0u : (mr & 7u);
    uint32_t exp_norm  = exp - 120u + carry;

    // subnormal path (117 <= exp <= 120)
    uint32_t full = (1u << 23) | mant;
    int shi = 141 - (int)exp;
    if (shi < 1)  shi = 1;
    if (shi > 24) shi = 24;
    uint32_t sh = (uint32_t)shi;
    uint32_t kept_s = full >> sh;
    uint32_t Rs = (full >> (sh - 1u)) & 1u;
    uint32_t Ss = (full & ((1u << (sh - 1u)) - 1u)) != 0u;
    uint32_t Ls = kept_s & 1u;
    uint32_t ms = kept_s + (Rs & (Ss | Ls));
    uint32_t sub_exp  = (ms >= 8u) ? 1u : 0u;
    uint32_t sub_mant = (ms >= 8u) ? 0u : ms;

    uint32_t exp8, mant8;
    if (exp > 134u)                      { exp8 = 15u;      mant8 = 6u;        }
    else if (exp >= 117u && exp <= 120u) { exp8 = sub_exp;  mant8 = sub_mant;  }
    else if (exp < 117u)                 { exp8 = 0u;       mant8 = 0u;        }
    else                                 { exp8 = exp_norm; mant8 = mant_norm; }

    o0.x = (float)s;
    o0.y = (float)((exp8 >> 3) & 1u);
    o0.z = (float)((exp8 >> 2) & 1u);
    o0.w = (float)((exp8 >> 1) & 1u);
    o1.x = (float)(exp8 & 1u);
    o1.y = (float)((mant8 >> 2) & 1u);
    o1.z = (float)((mant8 >> 1) & 1u);
    o1.w = (float)(mant8 & 1u);
}

__device__ __forceinline__ uint32_t nibble_of(uint4 v)
{
    return (((v.x >> 29) & 1u) << 3)
         | (((v.y >> 29) & 1u) << 2)
         | (((v.z >> 29) & 1u) << 1)
         |  ((v.w >> 29) & 1u);
}

__global__ __launch_bounds__(256) void fp32_to_fp8_pulse_kernel(
    const uint4* __restrict__ in,   // 8 x uint4 per row
    float4* __restrict__ out,       // 2 x float4 per row
    int nrows)
{
    __shared__ uint8_t snib[8][256];   // per-warp: 32 rows x 8 nibble-bytes

    const int warp      = threadIdx.x >> 5;
    const int lane      = threadIdx.x & 31;
    const int warpGlob  = blockIdx.x * 8 + warp;
    const int warpCount = gridDim.x * 8;
    const int nTiles    = nrows >> 5;

    for (int tile = warpGlob; tile < nTiles; tile += warpCount) {
        const uint4* tp = in + (size_t)tile * 256;

        // 8 coalesced streaming LDG.128; one nibble-byte store per lane-pass.
        // smem index p*32+lane == row-major (row=(p*32+lane)/8, col=%8).
#pragma unroll
        for (int p = 0; p < 8; p++) {
            uint4 v = __ldcs(&tp[p * 32 + lane]);
            snib[warp][p * 32 + lane] = (uint8_t)nibble_of(v);
        }
        __syncwarp();

        // lane r: one LDS.64 fetches row r's 8 nibble-bytes
        uint2 u = *reinterpret_cast<const uint2*>(&snib[warp][lane * 8]);

        uint32_t hi = ((u.x & 0x0000000Fu) << 28)
                    | ((u.x & 0x00000F00u) << 16)
                    | ((u.x & 0x000F0000u) << 4)
                    | ((u.x & 0x0F000000u) >> 8);
        uint32_t lo = ((u.y & 0x0000000Fu) << 12)
                    | ((u.y & 0x00000F00u) >> 0)
                    | ((u.y & 0x000F0000u) >> 12)
                    | ((u.y & 0x0F000000u) >> 24);
        uint32_t packed = hi | lo;

        float4 o0, o1;
        convert_row(packed, o0, o1);

        const int row = (tile << 5) + lane;
        __stcs(&out[(size_t)row * 2],     o0);
        __stcs(&out[(size_t)row * 2 + 1], o1);

        __syncwarp();   // snib reusable next iteration
    }

    // tail rows (nrows % 32), per-thread by global warp 0
    const int tailBase = nTiles << 5;
    if (warpGlob == 0) {
        for (int row = tailBase + lane; row < nrows; row += 32) {
            const uint4* p = in + (size_t)row * 8;
            uint32_t packed = 0;
#pragma unroll
            for (int k = 0; k < 8; k++)
                packed = (packed << 4) | nibble_of(__ldcs(&p[k]));
            float4 o0, o1;
            convert_row(packed, o0, o1);
            __stcs(&out[(size_t)row * 2],     o0);
            __stcs(&out[(size_t)row * 2 + 1], o1);
        }
    }
}

extern "C" void kernel_launch(void* const* d_in, const int* in_sizes, int n_in,
                              void* d_out, int out_size)
{
    const uint4* in = (const uint4*)d_in[0];
    float4* out = (float4*)d_out;
    int nrows = in_sizes[0] / 32;

    // one full wave: 148 SMs x 8 resident blocks (256 thr, ~32 regs)
    int blocks = 148 * 8;
    int nTiles = nrows >> 5;
    int maxBlocks = (nTiles + 7) / 8;            // never launch idle blocks
    if (blocks > maxBlocks && maxBlocks > 0) blocks = maxBlocks;
    if (blocks < 1) blocks = 1;
    fp32_to_fp8_pulse_kernel<<<blocks, 256>>>(in, out, nrows);
}

// round 7
// speedup vs baseline: 1.0786x; 1.0786x over previous
#include <cuda_runtime.h>
#include <stdint.h>

// FP32 bit-pulse -> FP8 E4M3 bit-pulse converter.
// Input : N*32 floats (0.0f/1.0f), row = [S, E7..E0, M22..M0] MSB first
// Output: N*8  floats, row = [S, E3..E0, M2..M0]
//
// Best-of-measured recombination:
//  - R3: warp owns 32 consecutive rows; EXPLICIT front-batch of all 8
//    coalesced LDG.128 (max MLP -> DRAM 84.8% measured) before the smem
//    nibble staging; transpose via 2KB smem nibble-bytes + one LDS.64/lane.
//  - R5: __ldcs/__stcs streaming hints (zero-reuse 256MB/64MB streams).
//  - 8192-block launch (hardware scheduler overlaps block drain/refill;
//    persistent variants measured worse).

__device__ __forceinline__ void convert_row(uint32_t packed,
                                            float4& o0, float4& o1)
{
    uint32_t s    = packed >> 31;
    uint32_t exp  = (packed >> 23) & 0xFFu;
    uint32_t mant = packed & 0x7FFFFFu;

    // normal path: RNE round 23 -> 3 mantissa bits
    uint32_t kept = mant >> 20;
    uint32_t R    = (mant >> 19) & 1u;
    uint32_t S    = (mant & ((1u << 19) - 1u)) != 0u;
    uint32_t L    = kept & 1u;
    uint32_t mr   = kept + (R & (S | L));
    uint32_t carry = mr >> 3;
    uint32_t mant_norm = carry ? 0u : (mr & 7u);
    uint32_t exp_norm  = exp - 120u + carry;

    // subnormal path (117 <= exp <= 120)
    uint32_t full = (1u << 23) | mant;
    int shi = 141 - (int)exp;
    if (shi < 1)  shi = 1;
    if (shi > 24) shi = 24;
    uint32_t sh = (uint32_t)shi;
    uint32_t kept_s = full >> sh;
    uint32_t Rs = (full >> (sh - 1u)) & 1u;
    uint32_t Ss = (full & ((1u << (sh - 1u)) - 1u)) != 0u;
    uint32_t Ls = kept_s & 1u;
    uint32_t ms = kept_s + (Rs & (Ss | Ls));
    uint32_t sub_exp  = (ms >= 8u) ? 1u : 0u;
    uint32_t sub_mant = (ms >= 8u) ? 0u : ms;

    uint32_t exp8, mant8;
    if (exp > 134u)                      { exp8 = 15u;      mant8 = 6u;        }
    else if (exp >= 117u && exp <= 120u) { exp8 = sub_exp;  mant8 = sub_mant;  }
    else if (exp < 117u)                 { exp8 = 0u;       mant8 = 0u;        }
    else                                 { exp8 = exp_norm; mant8 = mant_norm; }

    o0.x = (float)s;
    o0.y = (float)((exp8 >> 3) & 1u);
    o0.z = (float)((exp8 >> 2) & 1u);
    o0.w = (float)((exp8 >> 1) & 1u);
    o1.x = (float)(exp8 & 1u);
    o1.y = (float)((mant8 >> 2) & 1u);
    o1.z = (float)((mant8 >> 1) & 1u);
    o1.w = (float)(mant8 & 1u);
}

__device__ __forceinline__ uint32_t nibble_of(uint4 v)
{
    return (((v.x >> 29) & 1u) << 3)
         | (((v.y >> 29) & 1u) << 2)
         | (((v.z >> 29) & 1u) << 1)
         |  ((v.w >> 29) & 1u);
}

__global__ __launch_bounds__(256) void fp32_to_fp8_pulse_kernel(
    const uint4* __restrict__ in,   // 8 x uint4 per row
    float4* __restrict__ out,       // 2 x float4 per row
    int nrows)
{
    __shared__ uint8_t snib[8][256];   // per-warp: 32 rows x 8 nibble-bytes

    const int warp = threadIdx.x >> 5;
    const int lane = threadIdx.x & 31;
    const int baserow = (blockIdx.x * 8 + warp) * 32;
    if (baserow >= nrows) return;

    if (baserow + 32 <= nrows) {
        // ---- fast path: full 32-row tile ----
        const uint4* tile = in + (size_t)baserow * 8;

        // explicit front-batch: 8 independent coalesced LDG.128 (MLP=8)
        uint4 v[8];
#pragma unroll
        for (int p = 0; p < 8; p++) v[p] = __ldcs(&tile[p * 32 + lane]);

        // nibble staging: smem idx p*32+lane == row-major (row=idx/8,col=idx%8)
#pragma unroll
        for (int p = 0; p < 8; p++)
            snib[warp][p * 32 + lane] = (uint8_t)nibble_of(v[p]);
        __syncwarp();

        // lane r: one LDS.64 fetches row r's 8 nibble-bytes
        uint2 u = *reinterpret_cast<const uint2*>(&snib[warp][lane * 8]);

        uint32_t hi = ((u.x & 0x0000000Fu) << 28)
                    | ((u.x & 0x00000F00u) << 16)
                    | ((u.x & 0x000F0000u) << 4)
                    | ((u.x & 0x0F000000u) >> 8);
        uint32_t lo = ((u.y & 0x0000000Fu) << 12)
                    | ((u.y & 0x00000F00u) >> 0)
                    | ((u.y & 0x000F0000u) >> 12)
                    | ((u.y & 0x0F000000u) >> 24);
        uint32_t packed = hi | lo;

        float4 o0, o1;
        convert_row(packed, o0, o1);

        const int row = baserow + lane;
        __stcs(&out[(size_t)row * 2],     o0);
        __stcs(&out[(size_t)row * 2 + 1], o1);
    } else {
        // ---- tail path: per-thread row ----
        const int row = baserow + lane;
        if (row >= nrows) return;
        const uint4* p = in + (size_t)row * 8;
        uint32_t packed = 0;
#pragma unroll
        for (int k = 0; k < 8; k++)
            packed = (packed << 4) | nibble_of(__ldcs(&p[k]));
        float4 o0, o1;
        convert_row(packed, o0, o1);
        __stcs(&out[(size_t)row * 2],     o0);
        __stcs(&out[(size_t)row * 2 + 1], o1);
    }
}

extern "C" void kernel_launch(void* const* d_in, const int* in_sizes, int n_in,
                              void* d_out, int out_size)
{
    const uint4* in = (const uint4*)d_in[0];
    float4* out = (float4*)d_out;
    int nrows = in_sizes[0] / 32;

    int threads = 256;
    int blocks = (nrows + threads - 1) / threads;
    fp32_to_fp8_pulse_kernel<<<blocks, threads>>>(in, out, nrows);
}